// round 8
// baseline (speedup 1.0000x reference)
#include <cuda_runtime.h>
#include <cuda_bf16.h>

// Quantum circuit: N_QUBITS=10 (N=1024), N_LAYERS=5, out = U @ state per (b,c).
// R8: register-resident sim, 4 WARPS per state (CTA=128): 8 float2 regs/lane.
// Physical index p: bits 0-4 = lane, 5-7 = register, 8-9 = warp.
// All 50 gates unrolled; GF(2) CNOT-folded masks are immediates. Gates whose
// mask has a warp bit exchange via an 8KB smem buffer (+2 barriers); a
// compile-time basis transform B on the upper 5 bits minimizes how many.
//
// ENDIANNESS: qubit q (axis q+1) is bit (NQ-1-q) of the flattened index.

#define NQ      10
#define NST     1024
#define NLAYERS 5
#define NGATES  (NLAYERS * NQ)
#define NSTATES 2048          // 128 * 16
#define BLOCK   128
#define REGS    8

__host__ __device__ constexpr int highest_bit(unsigned v) {
    int h = 0; while (v >>= 1) h++; return h;
}
__host__ __device__ constexpr int parity10(unsigned x) {
    int p = 0;
    for (int k = 0; k < NQ; k++) p ^= (int)((x >> k) & 1u);
    return p;
}

struct M5 { unsigned r[5]; };   // 5x5 GF(2) matrix as row masks

__host__ __device__ constexpr M5 gf2inv5(M5 A) {
    unsigned a[5] = {}, b[5] = {};
    for (int i = 0; i < 5; i++) { a[i] = A.r[i]; b[i] = 1u << i; }
    for (int c = 0; c < 5; c++) {
        int p = c;
        for (int i = c; i < 5; i++) if ((a[i] >> c) & 1u) { p = i; break; }
        unsigned ta = a[c]; a[c] = a[p]; a[p] = ta;
        unsigned tb = b[c]; b[c] = b[p]; b[p] = tb;
        for (int i = 0; i < 5; i++)
            if (i != c && ((a[i] >> c) & 1u)) { a[i] ^= a[c]; b[i] ^= b[c]; }
    }
    M5 R{};
    for (int i = 0; i < 5; i++) R.r[i] = b[i];
    return R;
}

// rank({vs[0..n-1], cand}) == n+1 ?
__host__ __device__ constexpr bool indep(const unsigned* vs, int n, unsigned cand) {
    unsigned a[6] = {};
    for (int i = 0; i < n; i++) a[i] = vs[i];
    a[n] = cand;
    int rank = 0;
    for (int bit = 4; bit >= 0; bit--) {
        int piv = -1;
        for (int i = rank; i <= n; i++) if ((a[i] >> bit) & 1u) { piv = i; break; }
        if (piv < 0) continue;
        unsigned t = a[rank]; a[rank] = a[piv]; a[piv] = t;
        for (int i = 0; i <= n; i++)
            if (i != rank && ((a[i] >> bit) & 1u)) a[i] ^= a[rank];
        rank++;
    }
    return rank == n + 1;
}

struct Plan {
    unsigned m[NGATES];      // physical pair mask
    unsigned s[NGATES];      // physical parity mask
    unsigned lrow[32];       // load: v-row per preg = (warp<<3)|reg
    unsigned jreg[32];       // store: index contribution of (warp,reg)
    unsigned rlow[NQ];       // store: rows_final[b] & 31 (lane contribution)
};

// CNOT/gate recursion in vector-application order (reverse of build order),
// starting from phi = T (rows/cols pre-initialized).
__host__ __device__ constexpr void run_circuit(unsigned (&rows)[NQ], unsigned (&cols)[NQ],
                                               unsigned* m_out, unsigned* s_out) {
    int g = 0;
    for (int l = NLAYERS - 1; l >= 0; l--) {
        for (int q = NQ - 1; q >= 0; q--) {
            int c = NQ - 1 - q;                 // control bit
            int t = NQ - 1 - ((q + 1) % NQ);    // target bit
            rows[t] ^= rows[c];
            cols[c] ^= cols[t];
        }
        for (int q = NQ - 1; q >= 0; q--) {
            int b = NQ - 1 - q;
            if (m_out) m_out[g] = cols[b];
            if (s_out) s_out[g] = rows[b];
            g++;
        }
    }
}

__host__ __device__ constexpr Plan make_plan() {
    // Pass 1: identity basis -> raw masks, to choose the basis B.
    unsigned m0[NGATES] = {};
    {
        unsigned rows[NQ] = {}, cols[NQ] = {};
        for (int r = 0; r < NQ; r++) { rows[r] = 1u << r; cols[r] = 1u << r; }
        run_circuit(rows, cols, m0, nullptr);
    }
    // Choose Binv rows 3,4 (warp bits) minimizing # gates whose transformed
    // mask touches a warp bit. Distinct nonzero w3!=w4 are independent.
    unsigned bw3 = 1, bw4 = 2; int best = NGATES + 1;
    for (unsigned w3 = 1; w3 < 32; w3++) {
        for (unsigned w4 = w3 + 1; w4 < 32; w4++) {
            int cnt = 0;
            for (int g = 0; g < NGATES; g++) {
                unsigned mu = (m0[g] >> 5) & 31u;
                if (parity10(mu & w3) | parity10(mu & w4)) cnt++;
            }
            if (cnt < best) { best = cnt; bw3 = w3; bw4 = w4; }
        }
    }
    // Complete Binv to full rank.
    unsigned cur[5] = {bw3, bw4, 0, 0, 0};
    int have = 2;
    for (unsigned cand = 1; cand < 32 && have < 5; cand++)
        if (indep(cur, have, cand)) cur[have++] = cand;
    M5 Binv{};
    Binv.r[3] = bw3; Binv.r[4] = bw4;
    Binv.r[0] = cur[2]; Binv.r[1] = cur[3]; Binv.r[2] = cur[4];
    M5 B = gf2inv5(Binv);

    Plan P{};
    // Pass 2: full plan with phi initialized to T = diag(I5, B).
    unsigned rows[NQ] = {}, cols[NQ] = {};
    for (int b = 0; b < 5; b++) { rows[b] = 1u << b; cols[b] = 1u << b; }
    for (int i = 0; i < 5; i++) {
        rows[5 + i] = B.r[i] << 5;
        unsigned colv = 0;                       // column i of Binv
        for (int j = 0; j < 5; j++) colv |= ((Binv.r[j] >> i) & 1u) << j;
        cols[5 + i] = colv << 5;
    }
    run_circuit(rows, cols, P.m, P.s);

    // Load map: v-row for preg = B(preg).
    for (unsigned preg = 0; preg < 32; preg++) {
        unsigned R = 0;
        for (int i = 0; i < 5; i++) R |= (unsigned)parity10(preg & B.r[i]) << i;
        P.lrow[preg] = R;
    }
    // Store map: j = phi_final(p); bit b = parity(p & rows[b]).
    for (unsigned preg = 0; preg < 32; preg++) {
        unsigned j = 0;
        for (int b = 0; b < NQ; b++)
            j ^= (unsigned)parity10((preg << 5) & rows[b]) << b;
        P.jreg[preg] = j;
    }
    for (int b = 0; b < NQ; b++) P.rlow[b] = rows[b] & 31u;
    return P;
}

static constexpr Plan PLAN = make_plan();

__device__ float2 g_gates[NGATES][4];   // scratch (no allocation)

// Coefficients for applying G^T to the vector:
//   n0 =  cos(th/2)*a0          + e^{i ph} sin(th/2)*a1
//   n1 = -e^{i lm} sin(th/2)*a0 + e^{i(ph+lm)} cos(th/2)*a1
__global__ void prep_gates_kernel(const float* __restrict__ w, int w_elems) {
    int e = threadIdx.x;
    if (e >= NGATES) return;
    int l = (NLAYERS - 1) - e / NQ;     // matches plan emission order
    int q = (NQ - 1) - e % NQ;
    int base = (l * NQ + q) * 3;
    float th = 0.f, ph = 0.f, lm = 0.f;
    if (base + 2 < w_elems) { th = w[base]; ph = w[base + 1]; lm = w[base + 2]; }
    float c, s;
    sincosf(0.5f * th, &s, &c);
    float cp, sp;   sincosf(ph, &sp, &cp);
    float cl, sl;   sincosf(lm, &sl, &cl);
    float cpl, spl; sincosf(ph + lm, &spl, &cpl);
    g_gates[e][0] = make_float2(c, 0.0f);
    g_gates[e][1] = make_float2(cp * s, sp * s);
    g_gates[e][2] = make_float2(-cl * s, -sl * s);
    g_gates[e][3] = make_float2(cpl * c, spl * c);
}

__device__ __forceinline__ float2 bf(float2 a, float2 w, float2 cs, float2 cp) {
    float2 n;
    n.x = cs.x * a.x - cs.y * a.y + cp.x * w.x - cp.y * w.y;
    n.y = cs.x * a.y + cs.y * a.x + cp.x * w.y + cp.y * w.x;
    return n;
}

// Masks as template parameters (no PLAN access inside device code paths).
template <int G, unsigned M, unsigned S>
__device__ __forceinline__ void apply_gate(float2 (&v)[REGS], int lane, int wid,
                                           int tid, float2 (*sm)[BLOCK]) {
    constexpr unsigned ML = M & 31u;          // lane part
    constexpr unsigned MR = (M >> 5) & 7u;    // register part
    constexpr unsigned MW = (M >> 8) & 3u;    // warp part
    constexpr unsigned SL = S & 31u;
    constexpr unsigned SR = (S >> 5) & 7u;
    constexpr unsigned SW = (S >> 8) & 3u;

    const float2 c00 = __ldg(&g_gates[G][0]);
    const float2 c01 = __ldg(&g_gates[G][1]);
    const float2 c10 = __ldg(&g_gates[G][2]);
    const float2 c11 = __ldg(&g_gates[G][3]);

    // role(p) = parity(p & S) = CT reg-parity ^ runtime (lane,warp)-parity.
    const bool lw = ((__popc(lane & (int)SL) ^ __popc(wid & (int)SW)) & 1) != 0;
    const float2 cs0 = lw ? c11 : c00, cp0 = lw ? c10 : c01;  // reg-parity 0
    const float2 cs1 = lw ? c00 : c11, cp1 = lw ? c01 : c10;  // reg-parity 1

    if constexpr (MW != 0) {
        // Cross-warp gate: exchange via shared memory.
        __syncthreads();                       // buffer free from previous use
        #pragma unroll
        for (int r = 0; r < REGS; r++) sm[r][tid] = v[r];
        __syncthreads();
        const int ptid = tid ^ (int)(ML | (MW << 5));   // partner thread
        #pragma unroll
        for (int r = 0; r < REGS; r++) {
            float2 w = sm[r ^ (int)MR][ptid];
            const bool rp = (__popc((unsigned)r & SR) & 1) != 0;
            v[r] = bf(v[r], w, rp ? cs1 : cs0, rp ? cp1 : cp0);
        }
    } else if constexpr (MR == 0) {
        // partner in same register, other lane
        #pragma unroll
        for (int r = 0; r < REGS; r++) {
            float wx = __shfl_xor_sync(0xffffffffu, v[r].x, (int)ML);
            float wy = __shfl_xor_sync(0xffffffffu, v[r].y, (int)ML);
            const bool rp = (__popc((unsigned)r & SR) & 1) != 0;
            v[r] = bf(v[r], make_float2(wx, wy), rp ? cs1 : cs0, rp ? cp1 : cp0);
        }
    } else {
        constexpr int HB = highest_bit(MR);
        #pragma unroll
        for (int r = 0; r < REGS; r++) {
            if ((r >> HB) & 1) continue;          // each pair handled once
            const int r2 = r ^ (int)MR;
            float2 w, u;
            if constexpr (ML != 0) {
                w.x = __shfl_xor_sync(0xffffffffu, v[r2].x, (int)ML);
                w.y = __shfl_xor_sync(0xffffffffu, v[r2].y, (int)ML);
                u.x = __shfl_xor_sync(0xffffffffu, v[r].x,  (int)ML);
                u.y = __shfl_xor_sync(0xffffffffu, v[r].y,  (int)ML);
            } else {
                w = v[r2];
                u = v[r];
            }
            const float2 a = v[r], b = v[r2];
            const bool rpA = (__popc((unsigned)r  & SR) & 1) != 0;
            const bool rpB = (__popc((unsigned)r2 & SR) & 1) != 0;
            v[r]  = bf(a, w, rpA ? cs1 : cs0, rpA ? cp1 : cp0);
            v[r2] = bf(b, u, rpB ? cs1 : cs0, rpB ? cp1 : cp0);
        }
    }
}

template <int G>
struct GateSeq {
    static __device__ __forceinline__ void run(float2 (&v)[REGS], int lane, int wid,
                                               int tid, float2 (*sm)[BLOCK]) {
        apply_gate<G, PLAN.m[G], PLAN.s[G]>(v, lane, wid, tid, sm);
        GateSeq<G + 1>::run(v, lane, wid, tid, sm);
    }
};
template <>
struct GateSeq<NGATES> {
    static __device__ __forceinline__ void run(float2 (&)[REGS], int, int, int,
                                               float2 (*)[BLOCK]) {}
};

struct PParam {
    unsigned short lrow[32];
    unsigned short jreg[32];
    unsigned char  rlow[NQ];
};

template <int OUT_MODE>   // 0 = real-only float, 1 = interleaved float2
__global__ __launch_bounds__(BLOCK)
void sim_kernel(const float* __restrict__ x, int x_elems,
                void* __restrict__ outv, int out_size, PParam pp) {
    __shared__ float2 sm[REGS][BLOCK];

    const int tid  = threadIdx.x;
    const int lane = tid & 31;
    const int wid  = tid >> 5;
    const long long base = (long long)blockIdx.x * NST;

    float2 v[REGS];
    #pragma unroll
    for (int r = 0; r < REGS; r++) {
        int row = pp.lrow[(wid << 3) | r];
        long long gi = base + (row << 5) + lane;          // coalesced per warp
        v[r] = make_float2(gi < x_elems ? x[gi] : 0.0f, 0.0f);
    }

    GateSeq<0>::run(v, lane, wid, tid, sm);

    // out[phi(p)] = slot p ;  phi(p) = jreg(warp,reg) ^ jlane(lane)
    unsigned jl = 0;
    #pragma unroll
    for (int b = 0; b < NQ; b++)
        jl ^= (unsigned)((__popc(lane & (int)pp.rlow[b]) & 1) << b);

    #pragma unroll
    for (int r = 0; r < REGS; r++) {
        unsigned j = (unsigned)pp.jreg[(wid << 3) | r] ^ jl;
        long long oi = base + j;
        if (OUT_MODE == 0) {
            if (oi < out_size) ((float*)outv)[oi] = v[r].x;
        } else {
            if (2 * oi + 1 < out_size) ((float2*)outv)[oi] = v[r];
        }
    }
}

extern "C" void kernel_launch(void* const* d_in, const int* in_sizes, int n_in,
                              void* d_out, int out_size) {
    // Identify inputs by element count (robust to metadata ordering).
    const float* x_freq  = nullptr;  int x_elems = 0;
    const float* weights = nullptr;  int w_elems = 0;
    for (int i = 0; i < n_in; i++) {
        if (in_sizes[i] >= NSTATES * NST && !x_freq) {
            x_freq = (const float*)d_in[i]; x_elems = in_sizes[i];
        } else if (in_sizes[i] == NLAYERS * NQ * 3 && !weights) {
            weights = (const float*)d_in[i]; w_elems = in_sizes[i];
        }
    }
    if (!x_freq || !weights) {
        int big = 0;
        for (int i = 1; i < n_in; i++) if (in_sizes[i] > in_sizes[big]) big = i;
        x_freq = (const float*)d_in[big]; x_elems = in_sizes[big];
        int sm = (big == 0 && n_in > 1) ? 1 : 0;
        weights = (const float*)d_in[sm]; w_elems = in_sizes[sm];
    }

    prep_gates_kernel<<<1, 64>>>(weights, w_elems);

    PParam pp;
    for (int i = 0; i < 32; i++) pp.lrow[i] = (unsigned short)PLAN.lrow[i];
    for (int i = 0; i < 32; i++) pp.jreg[i] = (unsigned short)PLAN.jreg[i];
    for (int b = 0; b < NQ; b++) pp.rlow[b] = (unsigned char)PLAN.rlow[b];

    // out_size == 2M -> real float32 output; >= 4M -> interleaved complex64.
    if (out_size <= NSTATES * NST)
        sim_kernel<0><<<NSTATES, BLOCK>>>(x_freq, x_elems, d_out, out_size, pp);
    else
        sim_kernel<1><<<NSTATES, BLOCK>>>(x_freq, x_elems, d_out, out_size, pp);
}

// round 10
// speedup vs baseline: 1.0050x; 1.0050x over previous
#include <cuda_runtime.h>
#include <cuda_bf16.h>

// Quantum circuit: N_QUBITS=10 (N=1024), N_LAYERS=5, out = U @ state per (b,c).
// R10: register-resident sim, 2 warps/state, f32x2-PACKED amplitudes.
// Physical index p (after GF(2) basis transform T = diag(I5, B)):
//   bits 0-4 = lane, 5-7 = site (8 per lane), 8 = warp, 9 = PACK half.
// State per thread: X[s] = f32x2(re(p_half0), re(p_half1)), Y[s] = imag pack.
// Complex butterfly on 2 packed elements = 8 fma2/mul2 ops (4 per element,
// half the scalar-FFMA stream). Role difference between packed halves is a
// gate constant, folded into precomputed packed coefficient variants.
//
// ENDIANNESS: qubit q (axis q+1) is bit (NQ-1-q) of the flattened index.

#define NQ      10
#define NST     1024
#define NLAYERS 5
#define NGATES  (NLAYERS * NQ)
#define NSTATES 2048          // 128 * 16
#define BLOCK   64
#define SITES   8

typedef unsigned long long ull;

__host__ __device__ constexpr int highest_bit(unsigned v) {
    int h = 0; while (v >>= 1) h++; return h;
}
__host__ __device__ constexpr int parity10(unsigned x) {
    int p = 0;
    for (int k = 0; k < NQ; k++) p ^= (int)((x >> k) & 1u);
    return p;
}
__host__ __device__ constexpr int popc64(unsigned long long v) {
    int c = 0; while (v) { v &= v - 1; c++; } return c;
}

struct M5 { unsigned r[5]; };

__host__ __device__ constexpr M5 gf2inv5(M5 A) {
    unsigned a[5] = {}, b[5] = {};
    for (int i = 0; i < 5; i++) { a[i] = A.r[i]; b[i] = 1u << i; }
    for (int c = 0; c < 5; c++) {
        int p = c;
        for (int i = c; i < 5; i++) if ((a[i] >> c) & 1u) { p = i; break; }
        unsigned ta = a[c]; a[c] = a[p]; a[p] = ta;
        unsigned tb = b[c]; b[c] = b[p]; b[p] = tb;
        for (int i = 0; i < 5; i++)
            if (i != c && ((a[i] >> c) & 1u)) { a[i] ^= a[c]; b[i] ^= b[c]; }
    }
    M5 R{};
    for (int i = 0; i < 5; i++) R.r[i] = b[i];
    return R;
}

__host__ __device__ constexpr bool indep(const unsigned* vs, int n, unsigned cand) {
    unsigned a[6] = {};
    for (int i = 0; i < n; i++) a[i] = vs[i];
    a[n] = cand;
    int rank = 0;
    for (int bit = 4; bit >= 0; bit--) {
        int piv = -1;
        for (int i = rank; i <= n; i++) if ((a[i] >> bit) & 1u) { piv = i; break; }
        if (piv < 0) continue;
        unsigned t = a[rank]; a[rank] = a[piv]; a[piv] = t;
        for (int i = 0; i <= n; i++)
            if (i != rank && ((a[i] >> bit) & 1u)) a[i] ^= a[rank];
        rank++;
    }
    return rank == n + 1;
}

struct Plan {
    unsigned m[NGATES];      // physical pair mask
    unsigned s[NGATES];      // physical parity mask
    unsigned lrow[32];       // load: original row per upper-combo (pack<<4|warp<<3|site)
    unsigned jreg[32];       // store: index contribution of upper-combo
    unsigned rlow[NQ];       // store: rows_final[b] & 31 (lane contribution)
};

__host__ __device__ constexpr void run_circuit(unsigned (&rows)[NQ], unsigned (&cols)[NQ],
                                               unsigned* m_out, unsigned* s_out) {
    int g = 0;
    for (int l = NLAYERS - 1; l >= 0; l--) {
        for (int q = NQ - 1; q >= 0; q--) {
            int c = NQ - 1 - q;                 // control bit
            int t = NQ - 1 - ((q + 1) % NQ);    // target bit
            rows[t] ^= rows[c];
            cols[c] ^= cols[t];
        }
        for (int q = NQ - 1; q >= 0; q--) {
            int b = NQ - 1 - q;
            if (m_out) m_out[g] = cols[b];
            if (s_out) s_out[g] = rows[b];
            g++;
        }
    }
}

__host__ __device__ constexpr Plan make_plan() {
    // Pass 1: identity basis, raw masks, to choose B.
    unsigned m0[NGATES] = {};
    {
        unsigned rows[NQ] = {}, cols[NQ] = {};
        for (int r = 0; r < NQ; r++) { rows[r] = 1u << r; cols[r] = 1u << r; }
        run_circuit(rows, cols, m0, nullptr);
    }
    // Cheap-search precompute: par5 table, per-mask gate bitsets + counts.
    unsigned char par5[32] = {};
    for (unsigned v = 0; v < 32; v++) {
        unsigned x = v; int p = 0;
        while (x) { p ^= (int)(x & 1u); x >>= 1; }
        par5[v] = (unsigned char)p;
    }
    unsigned mu[NGATES] = {};
    for (int g = 0; g < NGATES; g++) mu[g] = (m0[g] >> 5) & 31u;
    unsigned long long gmask[32] = {};
    int gcnt[32] = {};
    for (unsigned r = 1; r < 32; r++) {
        unsigned long long msk = 0; int c = 0;
        for (int g = 0; g < NGATES; g++)
            if (par5[mu[g] & r]) { msk |= 1ull << g; c++; }
        gmask[r] = msk; gcnt[r] = c;
    }
    // Binv row3 -> warp bit (smem+barriers, weight 4),
    // Binv row4 -> pack bit (cheap half-swaps, weight 1). Joint exhaustive.
    unsigned bw = 1, bp = 2; int bestc = 1 << 20;
    for (unsigned w = 1; w < 32; w++) {
        for (unsigned p = 1; p < 32; p++) {
            if (p == w) continue;
            int cost = 4 * gcnt[w] + popc64(gmask[p] & ~gmask[w]);
            if (cost < bestc) { bestc = cost; bw = w; bp = p; }
        }
    }
    unsigned cur[5] = {bw, bp, 0, 0, 0};
    int have = 2;
    for (unsigned cand = 1; cand < 32 && have < 5; cand++)
        if (indep(cur, have, cand)) cur[have++] = cand;
    M5 Binv{};
    Binv.r[3] = bw; Binv.r[4] = bp;
    Binv.r[0] = cur[2]; Binv.r[1] = cur[3]; Binv.r[2] = cur[4];
    M5 B = gf2inv5(Binv);

    Plan P{};
    // Pass 2: full plan with phi initialized to T = diag(I5, B).
    unsigned rows[NQ] = {}, cols[NQ] = {};
    for (int b = 0; b < 5; b++) { rows[b] = 1u << b; cols[b] = 1u << b; }
    for (int i = 0; i < 5; i++) {
        rows[5 + i] = B.r[i] << 5;
        unsigned colv = 0;                       // column i of Binv
        for (int j = 0; j < 5; j++) colv |= ((Binv.r[j] >> i) & 1u) << j;
        cols[5 + i] = colv << 5;
    }
    run_circuit(rows, cols, P.m, P.s);

    for (unsigned preg = 0; preg < 32; preg++) {
        unsigned R = 0;
        for (int i = 0; i < 5; i++) R |= (unsigned)parity10(preg & B.r[i]) << i;
        P.lrow[preg] = R;
    }
    for (unsigned preg = 0; preg < 32; preg++) {
        unsigned j = 0;
        for (int b = 0; b < NQ; b++)
            j ^= (unsigned)parity10((preg << 5) & rows[b]) << b;
        P.jreg[preg] = j;
    }
    for (int b = 0; b < NQ; b++) P.rlow[b] = rows[b] & 31u;
    return P;
}

static constexpr Plan PLAN = make_plan();

// ---------------- packed f32x2 helpers ----------------
__device__ __forceinline__ ull fma2(ull a, ull b, ull c) {
    ull d;
    asm("fma.rn.f32x2 %0, %1, %2, %3;" : "=l"(d) : "l"(a), "l"(b), "l"(c));
    return d;
}
__device__ __forceinline__ ull mul2(ull a, ull b) {
    ull d;
    asm("mul.rn.f32x2 %0, %1, %2;" : "=l"(d) : "l"(a), "l"(b));
    return d;
}
__device__ __forceinline__ ull packf(float lo, float hi) {
    ull d;
    asm("mov.b64 %0, {%1, %2};" : "=l"(d) : "f"(lo), "f"(hi));
    return d;
}
__device__ __forceinline__ void unpackf(float& lo, float& hi, ull v) {
    asm("mov.b64 {%0, %1}, %2;" : "=f"(lo), "=f"(hi) : "l"(v));
}
__device__ __forceinline__ ull swap64(ull v) { return (v << 32) | (v >> 32); }

// Packed gate coefficient variants. For variant v (= role of pack-half0):
//   k=0 CSX  k=1 CSYn  k=2 CSY  k=3 CPX  k=4 CPYn  k=5 CPY
__device__ ull g_packs[NGATES][2][6];

struct SPArr { unsigned char sp[NGATES]; };

// Coefficients for applying G^T to the vector:
//   n0 =  cos(th/2)*a0          + e^{i ph} sin(th/2)*a1
//   n1 = -e^{i lm} sin(th/2)*a0 + e^{i(ph+lm)} cos(th/2)*a1
__global__ void prep_gates_kernel(const float* __restrict__ w, int w_elems, SPArr spa) {
    int e = threadIdx.x;
    if (e >= NGATES) return;
    int l = (NLAYERS - 1) - e / NQ;     // matches plan emission order
    int q = (NQ - 1) - e % NQ;
    int base = (l * NQ + q) * 3;
    float th = 0.f, ph = 0.f, lm = 0.f;
    if (base + 2 < w_elems) { th = w[base]; ph = w[base + 1]; lm = w[base + 2]; }
    float c, s;
    sincosf(0.5f * th, &s, &c);
    float cp_, sp_;   sincosf(ph, &sp_, &cp_);
    float cl, sl;     sincosf(lm, &sl, &cl);
    float cpl, spl;   sincosf(ph + lm, &spl, &cpl);
    float2 c00 = make_float2(c, 0.0f);
    float2 c01 = make_float2(cp_ * s, sp_ * s);
    float2 c10 = make_float2(-cl * s, -sl * s);
    float2 c11 = make_float2(cpl * c, spl * c);

    int SP = spa.sp[e];
    for (int v = 0; v < 2; v++) {
        int r0 = v, r1 = v ^ SP;
        float2 cs0 = r0 ? c11 : c00;
        float2 cs1 = r1 ? c11 : c00;
        float2 cq0 = r0 ? c10 : c01;
        float2 cq1 = r1 ? c10 : c01;
        g_packs[e][v][0] = packf(cs0.x,  cs1.x);
        g_packs[e][v][1] = packf(-cs0.y, -cs1.y);
        g_packs[e][v][2] = packf(cs0.y,  cs1.y);
        g_packs[e][v][3] = packf(cq0.x,  cq1.x);
        g_packs[e][v][4] = packf(-cq0.y, -cq1.y);
        g_packs[e][v][5] = packf(cq0.y,  cq1.y);
    }
}

// Masks as template parameters.
template <int G, unsigned M, unsigned S>
__device__ __forceinline__ void apply_gate(ull (&X)[SITES], ull (&Y)[SITES],
                                           int lane, int wid, int tid,
                                           ull (*exX)[BLOCK], ull (*exY)[BLOCK]) {
    constexpr unsigned ML = M & 31u;
    constexpr unsigned MR = (M >> 5) & 7u;
    constexpr unsigned MW = (M >> 8) & 1u;
    constexpr unsigned MP = (M >> 9) & 1u;
    constexpr unsigned SL = S & 31u;
    constexpr unsigned SW = (S >> 8) & 1u;
    constexpr unsigned SR = (S >> 5) & 7u;

    const int beta = (__popc(lane & (int)SL) ^ (wid & (int)SW)) & 1;
    const ull* PA = &g_packs[G][beta][0];
    const ull* PB = &g_packs[G][beta ^ 1][0];
    const ull A0 = __ldg(PA + 0), A1 = __ldg(PA + 1), A2 = __ldg(PA + 2);
    const ull A3 = __ldg(PA + 3), A4 = __ldg(PA + 4), A5 = __ldg(PA + 5);
    const ull B0 = __ldg(PB + 0), B1 = __ldg(PB + 1), B2 = __ldg(PB + 2);
    const ull B3 = __ldg(PB + 3), B4 = __ldg(PB + 4), B5 = __ldg(PB + 5);

    // Update site s (reads only old self + given partner packs, writes self).
    auto upd = [&](int s, ull wX, ull wY) {
        const bool ct = parity10((unsigned)s & SR) != 0;   // folds: s is literal
        const ull CSX  = ct ? B0 : A0;
        const ull CSYn = ct ? B1 : A1;
        const ull CSY  = ct ? B2 : A2;
        const ull CPX  = ct ? B3 : A3;
        const ull CPYn = ct ? B4 : A4;
        const ull CPY  = ct ? B5 : A5;
        ull nX = fma2(CSX, X[s], fma2(CSYn, Y[s], fma2(CPX, wX, mul2(CPYn, wY))));
        ull nY = fma2(CSX, Y[s], fma2(CSY, X[s], fma2(CPX, wY, mul2(CPY, wX))));
        X[s] = nX; Y[s] = nY;
    };

    if constexpr (MW != 0) {
        // Cross-warp: exchange via smem.
        __syncthreads();
        #pragma unroll
        for (int s = 0; s < SITES; s++) { exX[s][tid] = X[s]; exY[s][tid] = Y[s]; }
        __syncthreads();
        const int ptid = tid ^ (int)(ML | (MW << 5));
        #pragma unroll
        for (int s = 0; s < SITES; s++) {
            ull wX = exX[s ^ (int)MR][ptid];
            ull wY = exY[s ^ (int)MR][ptid];
            if constexpr (MP) { wX = swap64(wX); wY = swap64(wY); }
            upd(s, wX, wY);
        }
    } else if constexpr (MR != 0) {
        constexpr int HB = highest_bit(MR);
        #pragma unroll
        for (int s = 0; s < SITES; s++) {
            if ((s >> HB) & 1) continue;
            const int s2 = s ^ (int)MR;
            ull aX = X[s], aY = Y[s], bX = X[s2], bY = Y[s2];
            if constexpr (ML != 0) {
                aX = __shfl_xor_sync(0xffffffffu, aX, (int)ML);
                aY = __shfl_xor_sync(0xffffffffu, aY, (int)ML);
                bX = __shfl_xor_sync(0xffffffffu, bX, (int)ML);
                bY = __shfl_xor_sync(0xffffffffu, bY, (int)ML);
            }
            if constexpr (MP) {
                aX = swap64(aX); aY = swap64(aY);
                bX = swap64(bX); bY = swap64(bY);
            }
            upd(s,  bX, bY);   // partner of s  lives at site s2
            upd(s2, aX, aY);   // partner of s2 lives at site s (old value)
        }
    } else if constexpr (ML != 0) {
        #pragma unroll
        for (int s = 0; s < SITES; s++) {
            ull wX = __shfl_xor_sync(0xffffffffu, X[s], (int)ML);
            ull wY = __shfl_xor_sync(0xffffffffu, Y[s], (int)ML);
            if constexpr (MP) { wX = swap64(wX); wY = swap64(wY); }
            upd(s, wX, wY);
        }
    } else {
        // Pack-only gate: partner is the other half of our own packed regs.
        #pragma unroll
        for (int s = 0; s < SITES; s++)
            upd(s, swap64(X[s]), swap64(Y[s]));
    }
}

template <int G>
struct GateSeq {
    static __device__ __forceinline__ void run(ull (&X)[SITES], ull (&Y)[SITES],
                                               int lane, int wid, int tid,
                                               ull (*exX)[BLOCK], ull (*exY)[BLOCK]) {
        apply_gate<G, PLAN.m[G], PLAN.s[G]>(X, Y, lane, wid, tid, exX, exY);
        GateSeq<G + 1>::run(X, Y, lane, wid, tid, exX, exY);
    }
};
template <>
struct GateSeq<NGATES> {
    static __device__ __forceinline__ void run(ull (&)[SITES], ull (&)[SITES],
                                               int, int, int,
                                               ull (*)[BLOCK], ull (*)[BLOCK]) {}
};

struct PParam {
    unsigned short lrow[32];
    unsigned short jreg[32];
    unsigned char  rlow[NQ];
};

template <int OUT_MODE>   // 0 = real-only float, 1 = interleaved float2
__global__ __launch_bounds__(BLOCK)
void sim_kernel(const float* __restrict__ x, int x_elems,
                void* __restrict__ outv, int out_size, PParam pp) {
    __shared__ ull exX[SITES][BLOCK];
    __shared__ ull exY[SITES][BLOCK];

    const int tid  = threadIdx.x;
    const int lane = tid & 31;
    const int wid  = tid >> 5;
    const long long base = (long long)blockIdx.x * NST;

    ull X[SITES], Y[SITES];
    #pragma unroll
    for (int s = 0; s < SITES; s++) {
        int r0 = pp.lrow[(0 << 4) | (wid << 3) | s];
        int r1 = pp.lrow[(1 << 4) | (wid << 3) | s];
        long long g0 = base + (r0 << 5) + lane;
        long long g1 = base + (r1 << 5) + lane;
        float x0 = (g0 < x_elems) ? x[g0] : 0.0f;
        float x1 = (g1 < x_elems) ? x[g1] : 0.0f;
        X[s] = packf(x0, x1);
        Y[s] = 0ull;
    }

    GateSeq<0>::run(X, Y, lane, wid, tid, exX, exY);

    unsigned jl = 0;
    #pragma unroll
    for (int b = 0; b < NQ; b++)
        jl ^= (unsigned)((__popc(lane & (int)pp.rlow[b]) & 1) << b);

    #pragma unroll
    for (int s = 0; s < SITES; s++) {
        unsigned j0 = (unsigned)pp.jreg[(0 << 4) | (wid << 3) | s] ^ jl;
        unsigned j1 = (unsigned)pp.jreg[(1 << 4) | (wid << 3) | s] ^ jl;
        float x0, x1, y0, y1;
        unpackf(x0, x1, X[s]);
        unpackf(y0, y1, Y[s]);
        long long o0 = base + j0, o1 = base + j1;
        if (OUT_MODE == 0) {
            if (o0 < out_size) ((float*)outv)[o0] = x0;
            if (o1 < out_size) ((float*)outv)[o1] = x1;
        } else {
            if (2 * o0 + 1 < out_size) ((float2*)outv)[o0] = make_float2(x0, y0);
            if (2 * o1 + 1 < out_size) ((float2*)outv)[o1] = make_float2(x1, y1);
        }
    }
}

extern "C" void kernel_launch(void* const* d_in, const int* in_sizes, int n_in,
                              void* d_out, int out_size) {
    const float* x_freq  = nullptr;  int x_elems = 0;
    const float* weights = nullptr;  int w_elems = 0;
    for (int i = 0; i < n_in; i++) {
        if (in_sizes[i] >= NSTATES * NST && !x_freq) {
            x_freq = (const float*)d_in[i]; x_elems = in_sizes[i];
        } else if (in_sizes[i] == NLAYERS * NQ * 3 && !weights) {
            weights = (const float*)d_in[i]; w_elems = in_sizes[i];
        }
    }
    if (!x_freq || !weights) {
        int big = 0;
        for (int i = 1; i < n_in; i++) if (in_sizes[i] > in_sizes[big]) big = i;
        x_freq = (const float*)d_in[big]; x_elems = in_sizes[big];
        int sm = (big == 0 && n_in > 1) ? 1 : 0;
        weights = (const float*)d_in[sm]; w_elems = in_sizes[sm];
    }

    SPArr spa;
    for (int g = 0; g < NGATES; g++) spa.sp[g] = (unsigned char)((PLAN.s[g] >> 9) & 1u);
    prep_gates_kernel<<<1, 64>>>(weights, w_elems, spa);

    PParam pp;
    for (int i = 0; i < 32; i++) pp.lrow[i] = (unsigned short)PLAN.lrow[i];
    for (int i = 0; i < 32; i++) pp.jreg[i] = (unsigned short)PLAN.jreg[i];
    for (int b = 0; b < NQ; b++) pp.rlow[b] = (unsigned char)PLAN.rlow[b];

    // out_size == 2M -> real float32 output; >= 4M -> interleaved complex64.
    if (out_size <= NSTATES * NST)
        sim_kernel<0><<<NSTATES, BLOCK>>>(x_freq, x_elems, d_out, out_size, pp);
    else
        sim_kernel<1><<<NSTATES, BLOCK>>>(x_freq, x_elems, d_out, out_size, pp);
}